// round 1
// baseline (speedup 1.0000x reference)
#include <cuda_runtime.h>

#define N_QUBITS 7
#define DIM 128
#define DEPTH 2
#define NTHETA (DEPTH * N_QUBITS)

// Precomputed cos/sin of theta/2 (prep kernel fills this; no allocations).
__device__ float g_cs[2 * NTHETA];

__global__ void qnat_prep_kernel(const float* __restrict__ theta) {
    int i = threadIdx.x;
    if (i < NTHETA) {
        float s, c;
        sincosf(theta[i] * 0.5f, &s, &c);
        g_cs[i] = c;
        g_cs[i + NTHETA] = s;
    }
}

// One warp per row. Lane l holds amplitudes idx = l*4 + k, k in 0..3.
// bit0 of idx = k&1, bit1 = k>>1, bits 2..6 = lane bits 0..4.
__global__ void __launch_bounds__(256)
qnat_main_kernel(const float* __restrict__ embed,
                 float* __restrict__ out,
                 int nrows) {
    __shared__ float cs[2 * NTHETA];
    if (threadIdx.x < 2 * NTHETA) cs[threadIdx.x] = g_cs[threadIdx.x];
    __syncthreads();

    const int lane = threadIdx.x & 31;
    const int wib  = threadIdx.x >> 5;
    const long long row = (long long)blockIdx.x * 8 + wib;
    if (row >= nrows) return;

    // Coalesced: warp reads 512 contiguous bytes.
    float4 t = reinterpret_cast<const float4*>(embed + row * DIM)[lane];
    float v0 = t.x, v1 = t.y, v2 = t.z, v3 = t.w;

    // ---- normalize ----
    float ss = v0 * v0 + v1 * v1 + v2 * v2 + v3 * v3;
    #pragma unroll
    for (int m = 16; m >= 1; m >>= 1)
        ss += __shfl_xor_sync(0xffffffffu, ss, m);
    float inv = rsqrtf(ss);
    v0 *= inv; v1 *= inv; v2 *= inv; v3 *= inv;

    // ---- 2 depths of 7 RY rotations ----
    #pragma unroll
    for (int d = 0; d < DEPTH; d++) {
        // qubit 0: intra-lane pairs (v0,v1), (v2,v3)
        {
            float c = cs[d * N_QUBITS + 0];
            float s = cs[NTHETA + d * N_QUBITS + 0];
            float n0 = c * v0 - s * v1, n1 = s * v0 + c * v1;
            float n2 = c * v2 - s * v3, n3 = s * v2 + c * v3;
            v0 = n0; v1 = n1; v2 = n2; v3 = n3;
        }
        // qubit 1: intra-lane pairs (v0,v2), (v1,v3)
        {
            float c = cs[d * N_QUBITS + 1];
            float s = cs[NTHETA + d * N_QUBITS + 1];
            float n0 = c * v0 - s * v2, n2 = s * v0 + c * v2;
            float n1 = c * v1 - s * v3, n3 = s * v1 + c * v3;
            v0 = n0; v1 = n1; v2 = n2; v3 = n3;
        }
        // qubits 2..6: cross-lane butterflies
        #pragma unroll
        for (int q = 2; q < N_QUBITS; q++) {
            float c = cs[d * N_QUBITS + q];
            float s = cs[NTHETA + d * N_QUBITS + q];
            int m = 1 << (q - 2);
            float p0 = __shfl_xor_sync(0xffffffffu, v0, m);
            float p1 = __shfl_xor_sync(0xffffffffu, v1, m);
            float p2 = __shfl_xor_sync(0xffffffffu, v2, m);
            float p3 = __shfl_xor_sync(0xffffffffu, v3, m);
            if (lane & m) {
                // this lane holds the bit=1 amplitude: new = s*a0 + c*a1
                v0 = s * p0 + c * v0;
                v1 = s * p1 + c * v1;
                v2 = s * p2 + c * v2;
                v3 = s * p3 + c * v3;
            } else {
                // bit=0 amplitude: new = c*a0 - s*a1
                v0 = c * v0 - s * p0;
                v1 = c * v1 - s * p1;
                v2 = c * v2 - s * p2;
                v3 = c * v3 - s * p3;
            }
        }
        // CZ phase: only matters after depth 0 (the final CZ is erased by squaring)
        if (d == 0) {
            #pragma unroll
            for (int k = 0; k < 4; k++) {
                int idx = lane * 4 + k;
                int par = __popc(idx & (idx >> 1) & 0x3F) & 1;
                float sgn = par ? -1.0f : 1.0f;
                if (k == 0) v0 *= sgn;
                else if (k == 1) v1 *= sgn;
                else if (k == 2) v2 *= sgn;
                else v3 *= sgn;
            }
        }
    }

    // ---- probabilities & Z expectations ----
    float p0 = v0 * v0, p1 = v1 * v1, p2 = v2 * v2, p3 = v3 * v3;

    float acc[N_QUBITS];
    {
        float tsum = p0 + p1 + p2 + p3;
        acc[0] = p0 - p1 + p2 - p3;          // bit0 = k&1
        acc[1] = p0 + p1 - p2 - p3;          // bit1 = k>>1
        #pragma unroll
        for (int j = 2; j < N_QUBITS; j++)   // bit j from lane bit (j-2)
            acc[j] = ((lane >> (j - 2)) & 1) ? -tsum : tsum;
    }
    #pragma unroll
    for (int m = 16; m >= 1; m >>= 1) {
        #pragma unroll
        for (int j = 0; j < N_QUBITS; j++)
            acc[j] += __shfl_xor_sync(0xffffffffu, acc[j], m);
    }

    if (lane == 0) {
        float* o = out + row * N_QUBITS;
        #pragma unroll
        for (int j = 0; j < N_QUBITS; j++) o[j] = acc[j];
    }
}

extern "C" void kernel_launch(void* const* d_in, const int* in_sizes, int n_in,
                              void* d_out, int out_size) {
    const float* embed = (const float*)d_in[0];
    const float* theta = (const float*)d_in[1];
    float* out = (float*)d_out;

    int nrows = in_sizes[0] / DIM;

    qnat_prep_kernel<<<1, 32>>>(theta);

    int rows_per_block = 8;  // 256 threads = 8 warps
    int grid = (nrows + rows_per_block - 1) / rows_per_block;
    qnat_main_kernel<<<grid, 256>>>(embed, out, nrows);
}

// round 2
// speedup vs baseline: 1.0580x; 1.0580x over previous
#include <cuda_runtime.h>

#define N_QUBITS 7
#define DIM 128
#define DEPTH 2
#define NTHETA (DEPTH * N_QUBITS)

// Precomputed cos/sin of theta/2 (prep kernel fills this; no allocations).
__device__ float g_cs[2 * NTHETA];

__global__ void qnat_prep_kernel(const float* __restrict__ theta) {
    int i = threadIdx.x;
    if (i < NTHETA) {
        float s, c;
        sincosf(theta[i] * 0.5f, &s, &c);
        g_cs[i] = c;
        g_cs[i + NTHETA] = s;
    }
}

// One warp per row. Lane l holds amplitudes idx = l*4 + k, k in 0..3.
// bit0 of idx = k&1, bit1 = k>>1, bits 2..6 = lane bits 0..4.
// Normalization is folded into the epilogue: U is orthogonal, so
// sum(probs') = ||e||^2 and out = num / sum(probs').
__global__ void __launch_bounds__(256)
qnat_main_kernel(const float* __restrict__ embed,
                 float* __restrict__ out,
                 int nrows) {
    __shared__ float cs[2 * NTHETA];
    if (threadIdx.x < 2 * NTHETA) cs[threadIdx.x] = g_cs[threadIdx.x];
    __syncthreads();

    const int lane = threadIdx.x & 31;
    const int wib  = threadIdx.x >> 5;
    const long long row = (long long)blockIdx.x * 8 + wib;
    if (row >= nrows) return;

    // Coalesced: warp reads 512 contiguous bytes.
    float4 t4 = reinterpret_cast<const float4*>(embed + row * DIM)[lane];
    float v0 = t4.x, v1 = t4.y, v2 = t4.z, v3 = t4.w;

    // ---- 2 depths of 7 RY rotations (no upfront normalization) ----
    #pragma unroll
    for (int d = 0; d < DEPTH; d++) {
        // qubit 0: intra-lane pairs (v0,v1), (v2,v3)
        {
            float c = cs[d * N_QUBITS + 0];
            float s = cs[NTHETA + d * N_QUBITS + 0];
            float n0 = fmaf(-s, v1, c * v0), n1 = fmaf(c, v1, s * v0);
            float n2 = fmaf(-s, v3, c * v2), n3 = fmaf(c, v3, s * v2);
            v0 = n0; v1 = n1; v2 = n2; v3 = n3;
        }
        // qubit 1: intra-lane pairs (v0,v2), (v1,v3)
        {
            float c = cs[d * N_QUBITS + 1];
            float s = cs[NTHETA + d * N_QUBITS + 1];
            float n0 = fmaf(-s, v2, c * v0), n2 = fmaf(c, v2, s * v0);
            float n1 = fmaf(-s, v3, c * v1), n3 = fmaf(c, v3, s * v1);
            v0 = n0; v1 = n1; v2 = n2; v3 = n3;
        }
        // qubits 2..6: cross-lane butterflies (4 SHFL each)
        #pragma unroll
        for (int q = 2; q < N_QUBITS; q++) {
            float c = cs[d * N_QUBITS + q];
            float s = cs[NTHETA + d * N_QUBITS + q];
            int m = 1 << (q - 2);
            // bit=1 lane: new = c*v + s*partner ; bit=0 lane: new = c*v - s*partner
            float s2 = (lane & m) ? s : -s;
            float p0 = __shfl_xor_sync(0xffffffffu, v0, m);
            float p1 = __shfl_xor_sync(0xffffffffu, v1, m);
            float p2 = __shfl_xor_sync(0xffffffffu, v2, m);
            float p3 = __shfl_xor_sync(0xffffffffu, v3, m);
            v0 = fmaf(s2, p0, c * v0);
            v1 = fmaf(s2, p1, c * v1);
            v2 = fmaf(s2, p2, c * v2);
            v3 = fmaf(s2, p3, c * v3);
        }
        // CZ phase after depth 0 only (final CZ is erased by squaring)
        if (d == 0) {
            #pragma unroll
            for (int k = 0; k < 4; k++) {
                int idx = lane * 4 + k;
                int par = __popc(idx & (idx >> 1) & 0x3F) & 1;
                float sgn = par ? -1.0f : 1.0f;
                if (k == 0) v0 *= sgn;
                else if (k == 1) v1 *= sgn;
                else if (k == 2) v2 *= sgn;
                else v3 *= sgn;
            }
        }
    }

    // ---- probabilities ----
    float p0 = v0 * v0, p1 = v1 * v1, p2 = v2 * v2, p3 = v3 * v3;
    float q01 = p0 + p1, q23 = p2 + p3;
    float q02 = p0 + p2, q13 = p1 + p3;
    float t  = q01 + q23;    // per-lane total -> FWHT -> denom + acc[2..6]
    float ta = q02 - q13;    // bit0 signed sum   -> out[0] numerator
    float tb = q01 - q23;    // bit1 signed sum   -> out[1] numerator

    // ---- joint reduction of ta (even lanes) / tb (odd lanes): 6 SHFL ----
    float ua = __shfl_xor_sync(0xffffffffu, ta, 1);
    float ub = __shfl_xor_sync(0xffffffffu, tb, 1);
    float u = (lane & 1) ? (tb + ub) : (ta + ua);
    #pragma unroll
    for (int m = 2; m <= 16; m <<= 1)
        u += __shfl_xor_sync(0xffffffffu, u, m);
    // now: even lanes hold sum(ta), odd lanes hold sum(tb)

    // ---- FWHT of t over 5 lane bits: 5 SHFL ----
    // final f(L) = sum_l (-1)^{popc(L&l)} t(l)
    float f = t;
    #pragma unroll
    for (int m = 1; m <= 16; m <<= 1) {
        float p = __shfl_xor_sync(0xffffffffu, f, m);
        f = (lane & m) ? (p - f) : (f + p);
    }
    // lane 0: denom = sum(t) = ||e||^2 ; lane 2^b: acc[2+b]

    float denom = __shfl_sync(0xffffffffu, f, 0);   // broadcast: 1 SHFL
    float inv = __fdividef(1.0f, denom);

    float* o = out + row * N_QUBITS;
    if (lane == 0)       { o[0] = u * inv; }
    else if (lane == 1)  { o[1] = u * inv; o[2] = f * inv; }
    else if (lane == 2)  { o[3] = f * inv; }
    else if (lane == 4)  { o[4] = f * inv; }
    else if (lane == 8)  { o[5] = f * inv; }
    else if (lane == 16) { o[6] = f * inv; }
}

extern "C" void kernel_launch(void* const* d_in, const int* in_sizes, int n_in,
                              void* d_out, int out_size) {
    const float* embed = (const float*)d_in[0];
    const float* theta = (const float*)d_in[1];
    float* out = (float*)d_out;

    int nrows = in_sizes[0] / DIM;

    qnat_prep_kernel<<<1, 32>>>(theta);

    int rows_per_block = 8;  // 256 threads = 8 warps
    int grid = (nrows + rows_per_block - 1) / rows_per_block;
    qnat_main_kernel<<<grid, 256>>>(embed, out, nrows);
}

// round 3
// speedup vs baseline: 1.3094x; 1.2376x over previous
#include <cuda_runtime.h>

#define N_QUBITS 7
#define DIM 128
#define DEPTH 2
#define NTHETA (DEPTH * N_QUBITS)

// Prep kernel writes cos/sin(theta/2) here; a D2D memcpy node moves it into
// constant memory so the main kernel reads it via the uniform (LDCU) path
// instead of burning L1tex/MIO wavefronts on shared-memory broadcasts.
__device__ float g_cs[2 * NTHETA];
__constant__ float c_cs[2 * NTHETA];

__global__ void qnat_prep_kernel(const float* __restrict__ theta) {
    int i = threadIdx.x;
    if (i < NTHETA) {
        float s, c;
        sincosf(theta[i] * 0.5f, &s, &c);
        g_cs[i] = c;
        g_cs[i + NTHETA] = s;
    }
}

__device__ __forceinline__ float sgnflip(float v, unsigned flag) {
    return __int_as_float(__float_as_int(v) ^ (flag << 31));
}

// One warp per row. Amplitude layout: reg index k = (k0,k1), lane bits L0..L4.
// Qubit<->bit mapping is permuted over time by swap ops; tracked statically.
//
// Rotation on the qubit sitting at r0: pairs (v0,v1),(v2,v3) — free (FMA only).
// Rotation at r1: pairs (v0,v2),(v1,v3) — free.
// SWAPROT(m, i): swap qubit at lane-bit m into r0 (2 SHFL) and rotate it.
__global__ void __launch_bounds__(256)
qnat_main_kernel(const float* __restrict__ embed,
                 float* __restrict__ out,
                 int nrows) {
    const int lane = threadIdx.x & 31;
    const long long row = (long long)blockIdx.x * 8 + (threadIdx.x >> 5);
    if (row >= nrows) return;

    float4 t4 = reinterpret_cast<const float4*>(embed + row * DIM)[lane];
    float v0 = t4.x, v1 = t4.y, v2 = t4.z, v3 = t4.w;

#define ROT0(i) do {                                                    \
        float c = c_cs[(i)], s = c_cs[(i) + NTHETA];                    \
        float n0 = c * v0 - s * v1, n1 = s * v0 + c * v1;               \
        float n2 = c * v2 - s * v3, n3 = s * v2 + c * v3;               \
        v0 = n0; v1 = n1; v2 = n2; v3 = n3;                             \
    } while (0)

#define ROT1(i) do {                                                    \
        float c = c_cs[(i)], s = c_cs[(i) + NTHETA];                    \
        float n0 = c * v0 - s * v2, n2 = s * v0 + c * v2;               \
        float n1 = c * v1 - s * v3, n3 = s * v1 + c * v3;               \
        v0 = n0; v1 = n1; v2 = n2; v3 = n3;                             \
    } while (0)

#define SWAPROT(m, i) do {                                              \
        float c = c_cs[(i)], s = c_cs[(i) + NTHETA];                    \
        bool hi = (lane & (m)) != 0;                                    \
        float xa = hi ? v0 : v1;                                        \
        float xb = hi ? v2 : v3;                                        \
        float ra = __shfl_xor_sync(0xffffffffu, xa, (m));               \
        float rb = __shfl_xor_sync(0xffffffffu, xb, (m));               \
        float a0 = hi ? ra : v0, a1 = hi ? v1 : ra;                     \
        float b0 = hi ? rb : v2, b1 = hi ? v3 : rb;                     \
        v0 = c * a0 - s * a1; v1 = s * a0 + c * a1;                     \
        v2 = c * b0 - s * b1; v3 = s * b0 + c * b1;                     \
    } while (0)

    // ---- depth 0 ----
    // start: r0=q0, r1=q1, L=(q2,q3,q4,q5,q6)
    ROT0(0);            // q0
    ROT1(1);            // q1
    SWAPROT(1, 2);      // q2 in, q0 -> L0
    SWAPROT(2, 3);      // q3 in, q2 -> L1
    SWAPROT(4, 4);      // q4 in, q3 -> L2
    SWAPROT(8, 5);      // q5 in, q4 -> L3
    SWAPROT(16, 6);     // q6 in, q5 -> L4
    // now: r0=q6, r1=q1, L=(q0,q2,q3,q4,q5)

    // ---- CZ after depth 0 (final CZ is erased by squaring) ----
    // parity = q0q1+q1q2+q2q3+q3q4+q4q5+q5q6
    //        = L0*r1 + r1*L1 + L1L2 + L2L3 + L3L4 + L4*r0
    {
        unsigned pb  = __popc(lane & (lane >> 1) & 14) & 1;  // L1L2+L2L3+L3L4
        unsigned p01 = (lane ^ (lane >> 1)) & 1;             // L0 ^ L1
        unsigned p4  = (lane >> 4) & 1;                      // L4
        v0 = sgnflip(v0, pb);
        v1 = sgnflip(v1, pb ^ p4);
        v2 = sgnflip(v2, pb ^ p01);
        v3 = sgnflip(v3, pb ^ p01 ^ p4);
    }

    // ---- depth 1 (rotations commute; cycle in current layout order) ----
    ROT0(13);           // q6 (theta[7+6])
    ROT1(8);            // q1
    SWAPROT(1, 7);      // q0 in, q6 -> L0
    SWAPROT(2, 9);      // q2 in, q0 -> L1
    SWAPROT(4, 10);     // q3 in, q2 -> L2
    SWAPROT(8, 11);     // q4 in, q3 -> L3
    SWAPROT(16, 12);    // q5 in, q4 -> L4
    // final: r0=q5, r1=q1, L0=q6, L1=q0, L2=q2, L3=q3, L4=q4

    // ---- probabilities & reductions ----
    float p0 = v0 * v0, p1 = v1 * v1, p2 = v2 * v2, p3 = v3 * v3;
    float q01 = p0 + p1, q23 = p2 + p3;
    float q02 = p0 + p2, q13 = p1 + p3;
    float t  = q01 + q23;   // -> FWHT: denom + lane-bit qubits
    float ta = q02 - q13;   // signed by k0 (r0=q5)
    float tb = q01 - q23;   // signed by k1 (r1=q1)

    // joint reduce ta (even lanes) / tb (odd lanes): 6 SHFL
    float ua = __shfl_xor_sync(0xffffffffu, ta, 1);
    float ub = __shfl_xor_sync(0xffffffffu, tb, 1);
    float u = (lane & 1) ? (tb + ub) : (ta + ua);
    #pragma unroll
    for (int m = 2; m <= 16; m <<= 1)
        u += __shfl_xor_sync(0xffffffffu, u, m);
    // even lanes: sum(ta)=q5 ; odd lanes: sum(tb)=q1

    // FWHT of t over 5 lane bits: 5 SHFL
    float f = t;
    #pragma unroll
    for (int m = 1; m <= 16; m <<= 1) {
        float p = __shfl_xor_sync(0xffffffffu, f, m);
        f = (lane & m) ? (p - f) : (f + p);
    }
    // lane 0: denom=||e||^2 ; lane 1:q6, 2:q0, 4:q2, 8:q3, 16:q4

    float denom = __shfl_sync(0xffffffffu, f, 0);
    float inv = __fdividef(1.0f, denom);

    // gather 7 outputs onto lanes 0..6, single coalesced store
    // o[0]=f@2, o[1]=u@1, o[2]=f@4, o[3]=f@8, o[4]=f@16, o[5]=u@0, o[6]=f@1
    int fsrc = (lane == 0) ? 2 : (lane == 2) ? 4 : (lane == 3) ? 8
             : (lane == 4) ? 16 : (lane == 6) ? 1 : 0;
    int usrc = (lane == 5) ? 0 : 1;
    float gf = __shfl_sync(0xffffffffu, f, fsrc);
    float gu = __shfl_sync(0xffffffffu, u, usrc);
    float res = (lane == 1 || lane == 5) ? gu : gf;
    if (lane < N_QUBITS)
        out[row * N_QUBITS + lane] = res * inv;

#undef ROT0
#undef ROT1
#undef SWAPROT
}

extern "C" void kernel_launch(void* const* d_in, const int* in_sizes, int n_in,
                              void* d_out, int out_size) {
    const float* embed = (const float*)d_in[0];
    const float* theta = (const float*)d_in[1];
    float* out = (float*)d_out;

    int nrows = in_sizes[0] / DIM;

    qnat_prep_kernel<<<1, 32>>>(theta);

    // Move coefficients into constant memory (graph-capturable D2D memcpy node).
    void* dst = nullptr;
    void* src = nullptr;
    cudaGetSymbolAddress(&dst, c_cs);
    cudaGetSymbolAddress(&src, g_cs);
    cudaMemcpyAsync(dst, src, sizeof(float) * 2 * NTHETA,
                    cudaMemcpyDeviceToDevice, 0);

    int grid = (nrows + 7) / 8;   // 8 warps (rows) per 256-thread block
    qnat_main_kernel<<<grid, 256>>>(embed, out, nrows);
}

// round 4
// speedup vs baseline: 2.8089x; 2.1452x over previous
#include <cuda_runtime.h>

#define N_QUBITS 7
#define DIM 128
#define DEPTH 2
#define NTHETA 14

typedef unsigned long long u64;

// Packed rotation coefficients, 64-bit f32x2 lanes (lo = .x):
// [0..13]=(c,c) [14..27]=(s,s) [28..41]=(-s,-s) [42..55]=(lo=-s, hi=+s)
__device__ u64 g_pk[4 * NTHETA];
__constant__ u64 c_pk[4 * NTHETA];

__global__ void qnat_prep_kernel(const float* __restrict__ theta) {
    int i = threadIdx.x;
    if (i < NTHETA) {
        float s, c;
        sincosf(theta[i] * 0.5f, &s, &c);
        u64 uc = __float_as_uint(c), us = __float_as_uint(s), un = __float_as_uint(-s);
        g_pk[i]              = (uc << 32) | uc;
        g_pk[NTHETA + i]     = (us << 32) | us;
        g_pk[2 * NTHETA + i] = (un << 32) | un;
        g_pk[3 * NTHETA + i] = (us << 32) | un;   // lo=-s, hi=+s
    }
}

__device__ __forceinline__ u64 fma2(u64 a, u64 b, u64 c) {
    u64 d; asm("fma.rn.f32x2 %0, %1, %2, %3;" : "=l"(d) : "l"(a), "l"(b), "l"(c)); return d;
}
__device__ __forceinline__ u64 mul2(u64 a, u64 b) {
    u64 d; asm("mul.rn.f32x2 %0, %1, %2;" : "=l"(d) : "l"(a), "l"(b)); return d;
}
__device__ __forceinline__ u64 add2(u64 a, u64 b) {
    u64 d; asm("add.rn.f32x2 %0, %1, %2;" : "=l"(d) : "l"(a), "l"(b)); return d;
}

// Thread-per-row. State: v[j] = (amp[2j], amp[2j+1]) packed f32x2, j = 0..63.
// Qubit q>=1 of amp index a maps to bit (q-1) of j; qubit 0 is the lo/hi split.
__global__ void __launch_bounds__(64, 5)
qnat_main_kernel(const float* __restrict__ embed,
                 float* __restrict__ out,
                 int nrows) {
    __shared__ ulonglong2 tile[2][32][32];   // [warp][row][16B chunk, XOR-swizzled]

    const int l = threadIdx.x & 31;
    const int w = threadIdx.x >> 5;
    const long long rowbase = ((long long)blockIdx.x * 2 + w) * 32;
    if (rowbase >= nrows) return;
    const int valid = (int)(((long long)nrows - rowbase) < 32 ? (nrows - rowbase) : 32);

    // ---- stage 32 rows, coalesced, via cp.async with XOR-16B swizzle ----
    const float4* src = reinterpret_cast<const float4*>(embed + rowbase * DIM);
    #pragma unroll
    for (int it = 0; it < 32; it++) {
        if (it < valid) {
            unsigned dst = (unsigned)__cvta_generic_to_shared(&tile[w][it][l ^ it]);
            const float4* s = src + it * 32 + l;
            asm volatile("cp.async.cg.shared.global [%0], [%1], 16;"
                         :: "r"(dst), "l"(s) : "memory");
        }
    }
    asm volatile("cp.async.commit_group;\ncp.async.wait_group 0;" ::: "memory");
    __syncwarp();
    if (l >= valid) return;

    // ---- own row into packed registers (conflict-free swizzled LDS.128) ----
    u64 v[64];
    #pragma unroll
    for (int i = 0; i < 32; i++) {
        ulonglong2 g = tile[w][l][i ^ l];
        v[2 * i]     = g.x;   // (amp 4i,   amp 4i+1)
        v[2 * i + 1] = g.y;   // (amp 4i+2, amp 4i+3)
    }

    // ---- 2 depths of 7 RY rotations + CZ between ----
    #pragma unroll 1
    for (int d = 0; d < DEPTH; d++) {
        const int t0 = d * N_QUBITS;
        // qubit 0 (internal lo/hi): w' = (c,c)*w + (-s,+s)*(hi,lo)
        {
            u64 cc = c_pk[t0], ns = c_pk[3 * NTHETA + t0];
            #pragma unroll
            for (int j = 0; j < 64; j++) {
                u64 sw = (v[j] << 32) | (v[j] >> 32);
                v[j] = fma2(ns, sw, mul2(cc, v[j]));
            }
        }
        // qubits 1..6: packed pairs (v[j], v[j+m]), m = 2^(q-1)
        #pragma unroll
        for (int q = 1; q < N_QUBITS; q++) {
            u64 cc = c_pk[t0 + q];
            u64 ss = c_pk[NTHETA + t0 + q];
            u64 nn = c_pk[2 * NTHETA + t0 + q];
            const int m = 1 << (q - 1);
            #pragma unroll
            for (int j = 0; j < 64; j++) {
                if (!(j & m)) {
                    u64 A = v[j], B = v[j + m];
                    v[j]     = fma2(nn, B, mul2(cc, A));
                    v[j + m] = fma2(cc, B, mul2(ss, A));
                }
            }
        }
        // CZ after depth 0 (final CZ erased by squaring): compile-time sign masks
        if (d == 0) {
            #pragma unroll
            for (int j = 0; j < 64; j++) {
                int tb = j & (j >> 1);                                   // bits 0..4
                int pj = (tb ^ (tb >> 1) ^ (tb >> 2) ^ (tb >> 3) ^ (tb >> 4)) & 1;
                int ph = pj ^ (j & 1);
                u64 mask = (pj ? 0x80000000ull : 0ull) |
                           (ph ? 0x8000000000000000ull : 0ull);
                if (mask) v[j] ^= mask;
            }
        }
    }

    // ---- probabilities (packed squares) ----
    #pragma unroll
    for (int j = 0; j < 64; j++) v[j] = mul2(v[j], v[j]);

    // ---- in-place packed subset-sum tree over the 6 bits of j ----
    // invariant per block @base size 2^k: v[base]=total, v[base+2^t]=sum{bit_t=1}
    #pragma unroll
    for (int k = 0; k < 6; k++) {
        const int m = 1 << k;
        #pragma unroll
        for (int base = 0; base < 64; base += 2 * m) {
            v[base] = add2(v[base], v[base + m]);       // total (old v[base+m] kept: bit-k subset)
            #pragma unroll
            for (int t = 0; t < k; t++)
                v[base + (1 << t)] = add2(v[base + (1 << t)], v[base + m + (1 << t)]);
        }
    }

    // ---- finalize: S, z0 from lo/hi split; z1..z6 from subset sums ----
    float lo = __uint_as_float((unsigned)v[0]);
    float hi = __uint_as_float((unsigned)(v[0] >> 32));
    float S   = lo + hi;
    float z0  = lo - hi;
    float inv = __fdividef(1.0f, S);

    float* o = out + (rowbase + l) * N_QUBITS;
    o[0] = z0 * inv;
    #pragma unroll
    for (int q = 1; q < N_QUBITS; q++) {
        u64 G = v[1 << (q - 1)];
        float gs = __uint_as_float((unsigned)G) + __uint_as_float((unsigned)(G >> 32));
        o[q] = fmaf(-2.0f * gs, inv, 1.0f);   // (S - 2*gs)/S
    }
}

extern "C" void kernel_launch(void* const* d_in, const int* in_sizes, int n_in,
                              void* d_out, int out_size) {
    const float* embed = (const float*)d_in[0];
    const float* theta = (const float*)d_in[1];
    float* out = (float*)d_out;

    int nrows = in_sizes[0] / DIM;

    qnat_prep_kernel<<<1, 32>>>(theta);

    void* dst = nullptr;
    void* src = nullptr;
    cudaGetSymbolAddress(&dst, c_pk);
    cudaGetSymbolAddress(&src, g_pk);
    cudaMemcpyAsync(dst, src, sizeof(u64) * 4 * NTHETA,
                    cudaMemcpyDeviceToDevice, 0);

    int nwarps = (nrows + 31) / 32;
    int grid = (nwarps + 1) / 2;     // 2 warps (64 threads) per block
    qnat_main_kernel<<<grid, 64>>>(embed, out, nrows);
}

// round 5
// speedup vs baseline: 3.5740x; 1.2724x over previous
#include <cuda_runtime.h>

#define N_QUBITS 7
#define DIM 128
#define DEPTH 2
#define NTHETA 14

typedef unsigned long long u64;

// Tangent-form coefficients, t = tan(theta/2), packed f32x2 (lo = .x):
// [0..13]=(t,t)  [14..27]=(-t,-t)  [28..41]=(lo=-t, hi=+t)
// The cos factors cancel in out = num/denom (global scalar on all amps),
// so rotations need only FMAs.
__device__ u64 g_pk[3 * NTHETA];
__constant__ u64 c_pk[3 * NTHETA];

__global__ void qnat_prep_kernel(const float* __restrict__ theta) {
    int i = threadIdx.x;
    if (i < NTHETA) {
        float s, c;
        sincosf(theta[i] * 0.5f, &s, &c);
        float t = s / c;
        u64 ut = __float_as_uint(t), un = __float_as_uint(-t);
        g_pk[i]              = (ut << 32) | ut;   // (t, t)
        g_pk[NTHETA + i]     = (un << 32) | un;   // (-t, -t)
        g_pk[2 * NTHETA + i] = (ut << 32) | un;   // (lo=-t, hi=+t)
    }
}

__device__ __forceinline__ u64 fma2(u64 a, u64 b, u64 c) {
    u64 d; asm("fma.rn.f32x2 %0, %1, %2, %3;" : "=l"(d) : "l"(a), "l"(b), "l"(c)); return d;
}
__device__ __forceinline__ u64 mul2(u64 a, u64 b) {
    u64 d; asm("mul.rn.f32x2 %0, %1, %2;" : "=l"(d) : "l"(a), "l"(b)); return d;
}
__device__ __forceinline__ u64 add2(u64 a, u64 b) {
    u64 d; asm("add.rn.f32x2 %0, %1, %2;" : "=l"(d) : "l"(a), "l"(b)); return d;
}

// Thread-per-row. State: v[j] = (amp[2j], amp[2j+1]) packed f32x2, j = 0..63.
// Qubit q>=1 of amp index a maps to bit (q-1) of j; qubit 0 is the lo/hi split.
__global__ void __launch_bounds__(64, 5)
qnat_main_kernel(const float* __restrict__ embed,
                 float* __restrict__ out,
                 int nrows) {
    __shared__ ulonglong2 tile[2][32][32];   // [warp][row][16B chunk, XOR-swizzled]

    const int l = threadIdx.x & 31;
    const int w = threadIdx.x >> 5;
    const long long rowbase = ((long long)blockIdx.x * 2 + w) * 32;
    if (rowbase >= nrows) return;
    const int valid = (int)(((long long)nrows - rowbase) < 32 ? (nrows - rowbase) : 32);

    // ---- stage 32 rows, coalesced, via cp.async with XOR-16B swizzle ----
    const float4* src = reinterpret_cast<const float4*>(embed + rowbase * DIM);
    #pragma unroll
    for (int it = 0; it < 32; it++) {
        if (it < valid) {
            unsigned dst = (unsigned)__cvta_generic_to_shared(&tile[w][it][l ^ it]);
            const float4* s = src + it * 32 + l;
            asm volatile("cp.async.cg.shared.global [%0], [%1], 16;"
                         :: "r"(dst), "l"(s) : "memory");
        }
    }
    asm volatile("cp.async.commit_group;\ncp.async.wait_group 0;" ::: "memory");
    __syncwarp();
    if (l >= valid) return;

    // ---- own row into packed registers (conflict-free swizzled LDS.128) ----
    u64 v[64];
    #pragma unroll
    for (int i = 0; i < 32; i++) {
        ulonglong2 g = tile[w][l][i ^ l];
        v[2 * i]     = g.x;   // (amp 4i,   amp 4i+1)
        v[2 * i + 1] = g.y;   // (amp 4i+2, amp 4i+3)
    }

    // ---- 2 depths of 7 tangent-form RY rotations + CZ between ----
    #pragma unroll 1
    for (int d = 0; d < DEPTH; d++) {
        const int t0 = d * N_QUBITS;
        // qubit 0 (internal lo/hi): v' = v + (-t,+t)*(hi,lo)   [1 fma2 + swap]
        {
            u64 np = c_pk[2 * NTHETA + t0];
            #pragma unroll
            for (int j = 0; j < 64; j++) {
                u64 sw = (v[j] << 32) | (v[j] >> 32);
                v[j] = fma2(np, sw, v[j]);
            }
        }
        // qubits 1..6: A' = A - t*B ; B' = B + t*A   [2 fma2 per 4 amps]
        #pragma unroll
        for (int q = 1; q < N_QUBITS; q++) {
            u64 tt = c_pk[t0 + q];
            u64 nt = c_pk[NTHETA + t0 + q];
            const int m = 1 << (q - 1);
            #pragma unroll
            for (int j = 0; j < 64; j++) {
                if (!(j & m)) {
                    u64 A = v[j];
                    v[j]     = fma2(nt, v[j + m], A);
                    v[j + m] = fma2(tt, A, v[j + m]);
                }
            }
        }
        // CZ after depth 0 (final CZ erased by squaring): compile-time sign masks
        if (d == 0) {
            #pragma unroll
            for (int j = 0; j < 64; j++) {
                int tb = j & (j >> 1);                                   // bits 0..4
                int pj = (tb ^ (tb >> 1) ^ (tb >> 2) ^ (tb >> 3) ^ (tb >> 4)) & 1;
                int ph = pj ^ (j & 1);
                u64 mask = (pj ? 0x80000000ull : 0ull) |
                           (ph ? 0x8000000000000000ull : 0ull);
                if (mask) v[j] ^= mask;
            }
        }
    }

    // ---- probabilities (packed squares) ----
    #pragma unroll
    for (int j = 0; j < 64; j++) v[j] = mul2(v[j], v[j]);

    // ---- in-place packed subset-sum tree over the 6 bits of j ----
    // invariant per block @base size 2^k: v[base]=total, v[base+2^t]=sum{bit_t=1}
    #pragma unroll
    for (int k = 0; k < 6; k++) {
        const int m = 1 << k;
        #pragma unroll
        for (int base = 0; base < 64; base += 2 * m) {
            v[base] = add2(v[base], v[base + m]);       // total (old v[base+m] kept: bit-k subset)
            #pragma unroll
            for (int t = 0; t < k; t++)
                v[base + (1 << t)] = add2(v[base + (1 << t)], v[base + m + (1 << t)]);
        }
    }

    // ---- finalize: S, z0 from lo/hi split; z1..z6 from subset sums ----
    // (global Пc^2 factor cancels in the ratio)
    float lo = __uint_as_float((unsigned)v[0]);
    float hi = __uint_as_float((unsigned)(v[0] >> 32));
    float S   = lo + hi;
    float z0  = lo - hi;
    float inv = __fdividef(1.0f, S);

    float* o = out + (rowbase + l) * N_QUBITS;
    o[0] = z0 * inv;
    #pragma unroll
    for (int q = 1; q < N_QUBITS; q++) {
        u64 G = v[1 << (q - 1)];
        float gs = __uint_as_float((unsigned)G) + __uint_as_float((unsigned)(G >> 32));
        o[q] = fmaf(-2.0f * gs, inv, 1.0f);   // (S - 2*gs)/S
    }
}

extern "C" void kernel_launch(void* const* d_in, const int* in_sizes, int n_in,
                              void* d_out, int out_size) {
    const float* embed = (const float*)d_in[0];
    const float* theta = (const float*)d_in[1];
    float* out = (float*)d_out;

    int nrows = in_sizes[0] / DIM;

    qnat_prep_kernel<<<1, 32>>>(theta);

    void* dst = nullptr;
    void* src = nullptr;
    cudaGetSymbolAddress(&dst, c_pk);
    cudaGetSymbolAddress(&src, g_pk);
    cudaMemcpyAsync(dst, src, sizeof(u64) * 3 * NTHETA,
                    cudaMemcpyDeviceToDevice, 0);

    int nwarps = (nrows + 31) / 32;
    int grid = (nwarps + 1) / 2;     // 2 warps (64 threads) per block
    qnat_main_kernel<<<grid, 64>>>(embed, out, nrows);
}